// round 1
// baseline (speedup 1.0000x reference)
#include <cuda_runtime.h>
#include <math.h>

#define NNODES 50000
#define NEDGES 800000

// ---------------- scratch (static __device__ — no allocations) ----------------
__device__ __align__(16) float g_xl[NNODES * 128];
__device__ __align__(16) float g_xr[NNODES * 128];
__device__ __align__(16) float g_res[NNODES * 128];
__device__ __align__(16) float g_h1[NNODES * 32];
__device__ __align__(16) float g_h2[NNODES * 128];
__device__ __align__(16) float g_loop[NNODES * 8];
__device__ int g_deg[NNODES];
__device__ int g_rowptr[NNODES + 1];
__device__ int g_wptr[NNODES];
__device__ int g_colsrc[NEDGES];
__device__ int g_coleid[NEDGES];

// ---------------- CSR build ----------------
__global__ void hist_kernel(const int* __restrict__ dst, int* __restrict__ deg, int e) {
    int i = blockIdx.x * blockDim.x + threadIdx.x;
    if (i < e) atomicAdd(&deg[dst[i]], 1);
}

// single-block exclusive scan (warp-scan based), also seeds write cursors
__global__ void scan_kernel(const int* __restrict__ deg, int* __restrict__ rowptr,
                            int* __restrict__ wptr, int n) {
    __shared__ int warpsum[32];
    __shared__ int s_carry;
    int tid = threadIdx.x, lane = tid & 31, wid = tid >> 5;
    if (tid == 0) s_carry = 0;
    __syncthreads();
    for (int base = 0; base < n; base += 1024) {
        int i = base + tid;
        int v = (i < n) ? deg[i] : 0;
        int x = v;
        #pragma unroll
        for (int off = 1; off < 32; off <<= 1) {
            int t = __shfl_up_sync(0xffffffffu, x, off);
            if (lane >= off) x += t;
        }
        if (lane == 31) warpsum[wid] = x;
        __syncthreads();
        if (wid == 0) {
            int y = warpsum[lane];
            #pragma unroll
            for (int off = 1; off < 32; off <<= 1) {
                int t = __shfl_up_sync(0xffffffffu, y, off);
                if (lane >= off) y += t;
            }
            warpsum[lane] = y;
        }
        __syncthreads();
        int excl = x - v + (wid > 0 ? warpsum[wid - 1] : 0) + s_carry;
        if (i < n) { rowptr[i] = excl; wptr[i] = excl; }
        __syncthreads();                 // everyone has read s_carry
        if (tid == 0) s_carry += warpsum[31];
        __syncthreads();
    }
    if (threadIdx.x == 0) rowptr[n] = s_carry;
}

__global__ void scatter_kernel(const int* __restrict__ src, const int* __restrict__ dst,
                               int* __restrict__ wptr, int* __restrict__ colsrc,
                               int* __restrict__ coleid, int e) {
    int i = blockIdx.x * blockDim.x + threadIdx.x;
    if (i < e) {
        int d = dst[i];
        int p = atomicAdd(&wptr[d], 1);
        colsrc[p] = src[i];
        coleid[p] = i;
    }
}

// self-loop edge_attr = mean of incoming edge_attr. 8 lanes per dst (one per channel).
__global__ void loopattr_kernel(const int* __restrict__ rowptr, const int* __restrict__ coleid,
                                const float* __restrict__ eattr, float* __restrict__ loopattr,
                                int n) {
    int tid = blockIdx.x * blockDim.x + threadIdx.x;
    int g = tid >> 3;
    int c = tid & 7;
    if (g >= n) return;
    int rs = rowptr[g], re = rowptr[g + 1];
    float s = 0.f;
    for (int k = rs; k < re; k++) s += eattr[(size_t)coleid[k] * 8 + c];
    int d = re - rs;
    loopattr[g * 8 + c] = s / (float)(d > 0 ? d : 1);
}

// ---------------- dense GEMM: C[n,DOUT] = A[n,K] @ W[K,DOUT] + bias ----------------
template <int K, int DOUT>
__global__ __launch_bounds__(256) void gemm_bias(const float* __restrict__ A,
                                                 const float* __restrict__ W,
                                                 const float* __restrict__ bias,
                                                 float* __restrict__ C, int n) {
    constexpr int TPR  = DOUT / 4;       // threads per row
    constexpr int ROWS = 256 / TPR;      // rows per block
    constexpr int KP   = K + 1;          // pad to kill bank conflicts
    __shared__ float sW[K * DOUT];
    __shared__ float sA[ROWS * KP];
    int tid = threadIdx.x;
    for (int i = tid; i < K * DOUT; i += 256) sW[i] = W[i];
    int row0 = blockIdx.x * ROWS;
    for (int i = tid; i < ROWS * K; i += 256) {
        int rl = i / K, kk = i % K;
        int r = row0 + rl;
        sA[rl * KP + kk] = (r < n) ? A[(size_t)r * K + kk] : 0.f;
    }
    __syncthreads();
    int rlocal = tid / TPR, cseg = tid % TPR;
    int row = row0 + rlocal;
    if (row >= n) return;
    float acc[4];
    #pragma unroll
    for (int j = 0; j < 4; j++) acc[j] = bias ? bias[cseg + j * TPR] : 0.f;
    #pragma unroll
    for (int k = 0; k < K; k++) {
        float a = sA[rlocal * KP + k];
        #pragma unroll
        for (int j = 0; j < 4; j++)
            acc[j] = fmaf(a, sW[k * DOUT + cseg + j * TPR], acc[j]);
    }
    #pragma unroll
    for (int j = 0; j < 4; j++)
        C[(size_t)row * DOUT + cseg + j * TPR] = acc[j];
}

// ---------------- fused GATv2 edge pass: warp per destination node ----------------
// out[dst] = (sum_e w_e * xl[src_e]) / (sum_e w_e)  [+ bias] [+ pre] [relu]
// w_e = exp( att . leakyrelu(xl[src] + xr[dst] + We@eattr) ), per head.
// Channel map: reg j of lane l owns channel j*32+l. For CPH==32: head == j.
// For CPH==8 (D=32, R=1): head = lane/8, reduce within 8-lane groups.
template <int HEADS, int CPH, bool RELU>
__global__ __launch_bounds__(256) void agg_kernel(
    const float* __restrict__ xl, const float* __restrict__ xr,
    const float* __restrict__ edge_attr, const float* __restrict__ We,
    const float* __restrict__ att, const float* __restrict__ bias,
    const float* __restrict__ pre, const int* __restrict__ rowptr,
    const int* __restrict__ colsrc, const int* __restrict__ coleid,
    const float* __restrict__ loopattr, float* __restrict__ out, int n) {
    constexpr int D = HEADS * CPH;
    constexpr int R = D / 32;
    __shared__ float sWe[8 * D];
    int tid = threadIdx.x, lane = tid & 31, wid = tid >> 5;
    for (int i = tid; i < 8 * D; i += blockDim.x) sWe[i] = We[i];
    __syncthreads();

    int dst = blockIdx.x * (blockDim.x >> 5) + wid;
    if (dst >= n) return;

    float attv[R], xrv[R], num[R], den[R];
    #pragma unroll
    for (int j = 0; j < R; j++) {
        attv[j] = att[j * 32 + lane];
        xrv[j] = xr[(size_t)dst * D + j * 32 + lane];
        num[j] = 0.f;
        den[j] = 0.f;
    }

    int rs = rowptr[dst], re = rowptr[dst + 1];
    for (int k = rs - 1; k < re; k++) {
        int src;
        const float* ea;
        if (k < rs) {                       // virtual self loop
            src = dst;
            ea = loopattr + (size_t)dst * 8;
        } else {
            src = colsrc[k];
            ea = edge_attr + (size_t)coleid[k] * 8;
        }
        float4 ea0 = *(const float4*)ea;
        float4 ea1 = *(const float4*)(ea + 4);
        float eav[8] = {ea0.x, ea0.y, ea0.z, ea0.w, ea1.x, ea1.y, ea1.z, ea1.w};

        #pragma unroll
        for (int j = 0; j < R; j++) {
            int ch = j * 32 + lane;
            float xlv = xl[(size_t)src * D + ch];
            float ev = 0.f;
            #pragma unroll
            for (int q = 0; q < 8; q++) ev = fmaf(eav[q], sWe[q * D + ch], ev);
            float m = xlv + xrv[j] + ev;
            float s = fmaxf(m, 0.f) + 0.2f * fminf(m, 0.f);
            float p = s * attv[j];
            if (CPH == 32) {
                p += __shfl_xor_sync(0xffffffffu, p, 16);
                p += __shfl_xor_sync(0xffffffffu, p, 8);
                p += __shfl_xor_sync(0xffffffffu, p, 4);
                p += __shfl_xor_sync(0xffffffffu, p, 2);
                p += __shfl_xor_sync(0xffffffffu, p, 1);
            } else {  // CPH == 8: heads live in 8-lane groups
                p += __shfl_xor_sync(0xffffffffu, p, 4);
                p += __shfl_xor_sync(0xffffffffu, p, 2);
                p += __shfl_xor_sync(0xffffffffu, p, 1);
            }
            float w = __expf(p);
            num[j] = fmaf(w, xlv, num[j]);
            den[j] += w;
        }
    }

    #pragma unroll
    for (int j = 0; j < R; j++) {
        int ch = j * 32 + lane;
        float v = num[j] / den[j];
        if (bias) v += bias[ch];
        if (pre) v += pre[(size_t)dst * D + ch];
        if (RELU) v = fmaxf(v, 0.f);
        out[(size_t)dst * D + ch] = v;
    }
}

// ---------------- host launcher ----------------
extern "C" void kernel_launch(void* const* d_in, const int* in_sizes, int n_in,
                              void* d_out, int out_size) {
    const float* x     = (const float*)d_in[0];
    const int*   eidx  = (const int*)d_in[1];
    const float* eattr = (const float*)d_in[2];
    const float* Wl1 = (const float*)d_in[3];
    const float* bl1 = (const float*)d_in[4];
    const float* Wr1 = (const float*)d_in[5];
    const float* br1 = (const float*)d_in[6];
    const float* We1 = (const float*)d_in[7];
    const float* att1 = (const float*)d_in[8];
    const float* b1 = (const float*)d_in[9];
    const float* Wl2 = (const float*)d_in[10];
    const float* bl2 = (const float*)d_in[11];
    const float* Wr2 = (const float*)d_in[12];
    const float* br2 = (const float*)d_in[13];
    const float* We2 = (const float*)d_in[14];
    const float* att2 = (const float*)d_in[15];
    const float* b2 = (const float*)d_in[16];
    const float* Rw2 = (const float*)d_in[17];
    const float* Wl3 = (const float*)d_in[18];
    const float* bl3 = (const float*)d_in[19];
    const float* Wr3 = (const float*)d_in[20];
    const float* br3 = (const float*)d_in[21];
    const float* We3 = (const float*)d_in[22];
    const float* att3 = (const float*)d_in[23];
    const float* b3 = (const float*)d_in[24];

    int Nn = in_sizes[0] / 16;   // 50000
    int Ee = in_sizes[1] / 2;    // 800000
    const int* srcp = eidx;
    const int* dstp = eidx + Ee;

    float *xl, *xr, *res, *h1, *h2, *loopw;
    int *deg, *rowptr, *wptr, *colsrc, *coleid;
    cudaGetSymbolAddress((void**)&xl, g_xl);
    cudaGetSymbolAddress((void**)&xr, g_xr);
    cudaGetSymbolAddress((void**)&res, g_res);
    cudaGetSymbolAddress((void**)&h1, g_h1);
    cudaGetSymbolAddress((void**)&h2, g_h2);
    cudaGetSymbolAddress((void**)&loopw, g_loop);
    cudaGetSymbolAddress((void**)&deg, g_deg);
    cudaGetSymbolAddress((void**)&rowptr, g_rowptr);
    cudaGetSymbolAddress((void**)&wptr, g_wptr);
    cudaGetSymbolAddress((void**)&colsrc, g_colsrc);
    cudaGetSymbolAddress((void**)&coleid, g_coleid);

    // ---- CSR + self-loop attr ----
    cudaMemsetAsync(deg, 0, Nn * sizeof(int));
    hist_kernel<<<(Ee + 255) / 256, 256>>>(dstp, deg, Ee);
    scan_kernel<<<1, 1024>>>(deg, rowptr, wptr, Nn);
    scatter_kernel<<<(Ee + 255) / 256, 256>>>(srcp, dstp, wptr, colsrc, coleid, Ee);
    loopattr_kernel<<<(Nn * 8 + 255) / 256, 256>>>(rowptr, coleid, eattr, loopw, Nn);

    // ---- layer 1: in=16 -> D=32 (H=4, C=8), relu ----
    gemm_bias<16, 32><<<(Nn + 31) / 32, 256>>>(x, Wl1, bl1, xl, Nn);
    gemm_bias<16, 32><<<(Nn + 31) / 32, 256>>>(x, Wr1, br1, xr, Nn);
    agg_kernel<4, 8, true><<<(Nn + 7) / 8, 256>>>(xl, xr, eattr, We1, att1, b1, nullptr,
                                                  rowptr, colsrc, coleid, loopw, h1, Nn);

    // ---- layer 2: in=32 -> D=128 (H=4, C=32), residual h1@Rw2 + b2, relu ----
    gemm_bias<32, 128><<<(Nn + 7) / 8, 256>>>(h1, Wl2, bl2, xl, Nn);
    gemm_bias<32, 128><<<(Nn + 7) / 8, 256>>>(h1, Wr2, br2, xr, Nn);
    gemm_bias<32, 128><<<(Nn + 7) / 8, 256>>>(h1, Rw2, b2, res, Nn);
    agg_kernel<4, 32, true><<<(Nn + 7) / 8, 256>>>(xl, xr, eattr, We2, att2, nullptr, res,
                                                   rowptr, colsrc, coleid, loopw, h2, Nn);

    // ---- layer 3: in=128 -> D=32 (H=1, C=32), no relu ----
    gemm_bias<128, 32><<<(Nn + 31) / 32, 256>>>(h2, Wl3, bl3, xl, Nn);
    gemm_bias<128, 32><<<(Nn + 31) / 32, 256>>>(h2, Wr3, br3, xr, Nn);
    agg_kernel<1, 32, false><<<(Nn + 7) / 8, 256>>>(xl, xr, eattr, We3, att3, b3, nullptr,
                                                    rowptr, colsrc, coleid, loopw,
                                                    (float*)d_out, Nn);
}

// round 4
// speedup vs baseline: 1.4301x; 1.4301x over previous
#include <cuda_runtime.h>
#include <math.h>

#define NNODES 50000
#define NEDGES 800000

// ---------------- scratch (static __device__ — no allocations) ----------------
__device__ __align__(16) float g_xl[NNODES * 128];
__device__ __align__(16) float g_xr[NNODES * 128];
__device__ __align__(16) float g_res[NNODES * 128];
__device__ __align__(16) float g_h1[NNODES * 32];
__device__ __align__(16) float g_h2[NNODES * 128];
__device__ __align__(16) float g_loop[NNODES * 8];   // loop-attr sum, then mean (in place)
__device__ int g_deg[NNODES];
__device__ int g_rowptr[NNODES + 1];
__device__ int g_wptr[NNODES];
__device__ int g_bsum[1024];
__device__ int2 g_col[NEDGES];                       // {src, eid} per CSR slot

// ---------------- CSR build ----------------

// histogram + loop-attr accumulation in one pass
__global__ void hist2_kernel(const int* __restrict__ dst, const float* __restrict__ eattr,
                             int* __restrict__ deg, float* __restrict__ loopsum, int e) {
    int i = blockIdx.x * blockDim.x + threadIdx.x;
    if (i >= e) return;
    int d = dst[i];
    atomicAdd(&deg[d], 1);
    float4 a = *(const float4*)(eattr + (size_t)i * 8);
    float4 b = *(const float4*)(eattr + (size_t)i * 8 + 4);
    float* lp = loopsum + (size_t)d * 8;
    atomicAdd(lp + 0, a.x); atomicAdd(lp + 1, a.y);
    atomicAdd(lp + 2, a.z); atomicAdd(lp + 3, a.w);
    atomicAdd(lp + 4, b.x); atomicAdd(lp + 5, b.y);
    atomicAdd(lp + 6, b.z); atomicAdd(lp + 7, b.w);
}

__global__ void loopfin_kernel(const int* __restrict__ deg, float* __restrict__ loopv, int n8) {
    int i = blockIdx.x * blockDim.x + threadIdx.x;
    if (i >= n8) return;
    loopv[i] = loopv[i] / fmaxf((float)deg[i >> 3], 1.0f);
}

// per-block sums of deg
__global__ void blocksum_kernel(const int* __restrict__ deg, int* __restrict__ bsum, int n) {
    __shared__ int sh[32];
    int tid = threadIdx.x, lane = tid & 31, wid = tid >> 5;
    int i = blockIdx.x * 1024 + tid;
    int v = (i < n) ? deg[i] : 0;
    #pragma unroll
    for (int off = 16; off > 0; off >>= 1) v += __shfl_xor_sync(0xffffffffu, v, off);
    if (lane == 0) sh[wid] = v;
    __syncthreads();
    if (wid == 0) {
        int x = sh[lane];
        #pragma unroll
        for (int off = 16; off > 0; off >>= 1) x += __shfl_xor_sync(0xffffffffu, x, off);
        if (lane == 0) bsum[blockIdx.x] = x;
    }
}

// exclusive scan of <=1024 block sums (single block)
__global__ void scanpart_kernel(int* __restrict__ b, int g) {
    __shared__ int ws[32];
    int tid = threadIdx.x, lane = tid & 31, wid = tid >> 5;
    int v = (tid < g) ? b[tid] : 0;
    int x = v;
    #pragma unroll
    for (int off = 1; off < 32; off <<= 1) {
        int t = __shfl_up_sync(0xffffffffu, x, off);
        if (lane >= off) x += t;
    }
    if (lane == 31) ws[wid] = x;
    __syncthreads();
    if (wid == 0) {
        int y = ws[lane];
        #pragma unroll
        for (int off = 1; off < 32; off <<= 1) {
            int t = __shfl_up_sync(0xffffffffu, y, off);
            if (lane >= off) y += t;
        }
        ws[lane] = y;
    }
    __syncthreads();
    int excl = x - v + (wid > 0 ? ws[wid - 1] : 0);
    if (tid < g) b[tid] = excl;
}

// final: per-block exclusive scan + block offset -> rowptr & wptr
__global__ void scanfinal_kernel(const int* __restrict__ deg, const int* __restrict__ bsum,
                                 int* __restrict__ rowptr, int* __restrict__ wptr,
                                 int n, int e) {
    __shared__ int ws[32];
    int tid = threadIdx.x, lane = tid & 31, wid = tid >> 5;
    int i = blockIdx.x * 1024 + tid;
    int v = (i < n) ? deg[i] : 0;
    int x = v;
    #pragma unroll
    for (int off = 1; off < 32; off <<= 1) {
        int t = __shfl_up_sync(0xffffffffu, x, off);
        if (lane >= off) x += t;
    }
    if (lane == 31) ws[wid] = x;
    __syncthreads();
    if (wid == 0) {
        int y = ws[lane];
        #pragma unroll
        for (int off = 1; off < 32; off <<= 1) {
            int t = __shfl_up_sync(0xffffffffu, y, off);
            if (lane >= off) y += t;
        }
        ws[lane] = y;
    }
    __syncthreads();
    int excl = x - v + (wid > 0 ? ws[wid - 1] : 0) + bsum[blockIdx.x];
    if (i < n) { rowptr[i] = excl; wptr[i] = excl; }
    if (blockIdx.x == 0 && tid == 0) rowptr[n] = e;
}

__global__ void scatter_kernel(const int* __restrict__ src, const int* __restrict__ dst,
                               int* __restrict__ wptr, int2* __restrict__ col, int e) {
    int i = blockIdx.x * blockDim.x + threadIdx.x;
    if (i < e) {
        int d = dst[i];
        int p = atomicAdd(&wptr[d], 1);
        col[p] = make_int2(src[i], i);
    }
}

// ---------------- dense GEMM: O[n,DOUT] = A[n,K] @ W[K,DOUT] + b, up to NW weight sets ----------------
template <int K, int DOUT, int NW, int ROWS, int KC>
__global__ void gemm_multi(const float* __restrict__ A,
                           const float* __restrict__ W0, const float* __restrict__ b0, float* __restrict__ O0,
                           const float* __restrict__ W1, const float* __restrict__ b1, float* __restrict__ O1,
                           int n) {
    constexpr int COLS = DOUT * NW;
    constexpr int TX = COLS / 4;
    constexpr int TY = ROWS / 4;
    constexpr int NT = TX * TY;
    __shared__ float sW[K * COLS];
    __shared__ float sA[KC][ROWS + 1];
    int tid = threadIdx.x;
    for (int idx = tid; idx < K * DOUT; idx += NT) {
        int k = idx / DOUT, c = idx % DOUT;
        sW[k * COLS + c] = W0[idx];
        if (NW > 1) sW[k * COLS + DOUT + c] = W1[idx];
    }
    int tx = tid % TX, ty = tid / TX;
    int cg = tx * 4;
    int which = cg / DOUT, col = cg % DOUT;
    const float* bb = (which == 0) ? b0 : b1;
    int row0 = blockIdx.x * ROWS;

    float acc[4][4];
    #pragma unroll
    for (int i = 0; i < 4; i++)
        #pragma unroll
        for (int j = 0; j < 4; j++) acc[i][j] = bb[col + j];

    for (int kc0 = 0; kc0 < K; kc0 += KC) {
        __syncthreads();
        for (int idx = tid; idx < ROWS * KC; idx += NT) {
            int r = idx / KC, k = idx % KC;
            int gr = row0 + r;
            sA[k][r] = (gr < n) ? A[(size_t)gr * K + kc0 + k] : 0.f;
        }
        __syncthreads();
        #pragma unroll
        for (int k = 0; k < KC; k++) {
            float4 rb = *(const float4*)&sW[(kc0 + k) * COLS + cg];
            float ra0 = sA[k][ty * 4 + 0];
            float ra1 = sA[k][ty * 4 + 1];
            float ra2 = sA[k][ty * 4 + 2];
            float ra3 = sA[k][ty * 4 + 3];
            acc[0][0] = fmaf(ra0, rb.x, acc[0][0]); acc[0][1] = fmaf(ra0, rb.y, acc[0][1]);
            acc[0][2] = fmaf(ra0, rb.z, acc[0][2]); acc[0][3] = fmaf(ra0, rb.w, acc[0][3]);
            acc[1][0] = fmaf(ra1, rb.x, acc[1][0]); acc[1][1] = fmaf(ra1, rb.y, acc[1][1]);
            acc[1][2] = fmaf(ra1, rb.z, acc[1][2]); acc[1][3] = fmaf(ra1, rb.w, acc[1][3]);
            acc[2][0] = fmaf(ra2, rb.x, acc[2][0]); acc[2][1] = fmaf(ra2, rb.y, acc[2][1]);
            acc[2][2] = fmaf(ra2, rb.z, acc[2][2]); acc[2][3] = fmaf(ra2, rb.w, acc[2][3]);
            acc[3][0] = fmaf(ra3, rb.x, acc[3][0]); acc[3][1] = fmaf(ra3, rb.y, acc[3][1]);
            acc[3][2] = fmaf(ra3, rb.z, acc[3][2]); acc[3][3] = fmaf(ra3, rb.w, acc[3][3]);
        }
    }
    float* O = (which == 0) ? O0 : O1;
    #pragma unroll
    for (int i = 0; i < 4; i++) {
        int gr = row0 + ty * 4 + i;
        if (gr < n) {
            float4 v = make_float4(acc[i][0], acc[i][1], acc[i][2], acc[i][3]);
            *(float4*)&O[(size_t)gr * DOUT + col] = v;
        }
    }
}

// ---------------- fused GATv2 edge pass: warp per destination node ----------------
// Channel map: lane owns channels [lane*VEC, lane*VEC+VEC). Since heads are
// 32-channel contiguous, every lane's VEC channels belong to head lane*VEC/32,
// so the att-dot reduction is a butterfly over GROUP = 32*32*VEC/(32*D/H) lanes.
//   layer1: VEC=1, D=32, H=4  -> GROUP=8
//   layer2: VEC=4, D=128,H=4  -> GROUP=8  (lane's float4 all in head lane>>3)
//   layer3: VEC=1, D=32, H=1  -> GROUP=32
template <int VEC, int GROUP, bool RELU>
__global__ __launch_bounds__(256) void agg_kernel(
    const float* __restrict__ xl, const float* __restrict__ xr,
    const float* __restrict__ eattr, const float* __restrict__ We,
    const float* __restrict__ att, const float* __restrict__ bias,
    const float* __restrict__ pre, const int* __restrict__ rowptr,
    const int2* __restrict__ col, const float* __restrict__ loopattr,
    float* __restrict__ out, int n) {
    constexpr int D = 32 * VEC;
    __shared__ float sWe[8 * D];
    int tid = threadIdx.x, lane = tid & 31, wid = tid >> 5;
    for (int i = tid; i < 8 * D; i += 256) sWe[i] = We[i];
    __syncthreads();

    int dst = blockIdx.x * 8 + wid;
    if (dst >= n) return;

    const int c0 = lane * VEC;
    float rWe8[8];
    if (VEC == 1) {
        #pragma unroll
        for (int q = 0; q < 8; q++) rWe8[q] = sWe[q * 32 + lane];
    }
    float attv[VEC], xrv[VEC], num[VEC];
    float den = 0.f;
    if (VEC == 4) {
        float4 a = *(const float4*)(att + c0);
        attv[0] = a.x; attv[1] = a.y; attv[2] = a.z; attv[3] = a.w;
        float4 r = *(const float4*)(xr + (size_t)dst * D + c0);
        xrv[0] = r.x; xrv[1] = r.y; xrv[2] = r.z; xrv[3] = r.w;
    } else {
        attv[0] = att[c0];
        xrv[0] = xr[(size_t)dst * D + c0];
    }
    #pragma unroll
    for (int v = 0; v < VEC; v++) num[v] = 0.f;

    auto ldX = [&](float* d, const float* p) {
        if (VEC == 4) {
            float4 t = *(const float4*)p;
            d[0] = t.x; d[1] = t.y; d[2] = t.z; d[3] = t.w;
        } else d[0] = p[0];
    };
    auto ldE = [&](float* d, const float* p) {
        float4 a = *(const float4*)p;
        float4 b = *(const float4*)(p + 4);
        d[0] = a.x; d[1] = a.y; d[2] = a.z; d[3] = a.w;
        d[4] = b.x; d[5] = b.y; d[6] = b.z; d[7] = b.w;
    };
    auto body = [&](const float* xv, const float* ev) {
        float m[VEC];
        #pragma unroll
        for (int v = 0; v < VEC; v++) m[v] = 0.f;
        #pragma unroll
        for (int q = 0; q < 8; q++) {
            if (VEC == 4) {
                const float4 wq = *(const float4*)&sWe[q * D + c0];
                m[0] = fmaf(ev[q], wq.x, m[0]);
                m[1] = fmaf(ev[q], wq.y, m[1]);
                m[2] = fmaf(ev[q], wq.z, m[2]);
                m[3] = fmaf(ev[q], wq.w, m[3]);
            } else {
                m[0] = fmaf(ev[q], rWe8[q], m[0]);
            }
        }
        float p = 0.f;
        #pragma unroll
        for (int v = 0; v < VEC; v++) {
            float t = m[v] + xv[v] + xrv[v];
            float s = fmaxf(t, 0.f) + 0.2f * fminf(t, 0.f);
            p = fmaf(s, attv[v], p);
        }
        #pragma unroll
        for (int off = GROUP / 2; off > 0; off >>= 1)
            p += __shfl_xor_sync(0xffffffffu, p, off);
        float w = __expf(p);
        #pragma unroll
        for (int v = 0; v < VEC; v++) num[v] = fmaf(w, xv[v], num[v]);
        den += w;
    };

    int rs = rowptr[dst], re = rowptr[dst + 1];
    int k = rs;
    float pxl[VEC], pea[8];
    if (k < re) {                               // prefetch first real edge
        int2 nm = col[k];
        ldE(pea, eattr + (size_t)nm.y * 8);
        ldX(pxl, xl + (size_t)nm.x * D + c0);
    }
    {                                           // self loop (overlaps prefetch)
        float sx[VEC], se[8];
        ldX(sx, xl + (size_t)dst * D + c0);
        ldE(se, loopattr + (size_t)dst * 8);
        body(sx, se);
    }
    while (k < re) {
        float cx[VEC], ce[8];
        #pragma unroll
        for (int v = 0; v < VEC; v++) cx[v] = pxl[v];
        #pragma unroll
        for (int q = 0; q < 8; q++) ce[q] = pea[q];
        k++;
        if (k < re) {
            int2 nm = col[k];
            ldE(pea, eattr + (size_t)nm.y * 8);
            ldX(pxl, xl + (size_t)nm.x * D + c0);
        }
        body(cx, ce);
    }

    float res[VEC];
    #pragma unroll
    for (int v = 0; v < VEC; v++) {
        float val = num[v] / den;
        if (bias) val += bias[c0 + v];
        if (pre) val += pre[(size_t)dst * D + c0 + v];
        if (RELU) val = fmaxf(val, 0.f);
        res[v] = val;
    }
    if (VEC == 4) {
        *(float4*)&out[(size_t)dst * D + c0] = make_float4(res[0], res[1], res[2], res[3]);
    } else {
        out[(size_t)dst * D + c0] = res[0];
    }
}

// ---------------- host launcher ----------------
extern "C" void kernel_launch(void* const* d_in, const int* in_sizes, int n_in,
                              void* d_out, int out_size) {
    const float* x     = (const float*)d_in[0];
    const int*   eidx  = (const int*)d_in[1];
    const float* eattr = (const float*)d_in[2];
    const float* Wl1 = (const float*)d_in[3];
    const float* bl1 = (const float*)d_in[4];
    const float* Wr1 = (const float*)d_in[5];
    const float* br1 = (const float*)d_in[6];
    const float* We1 = (const float*)d_in[7];
    const float* att1 = (const float*)d_in[8];
    const float* b1 = (const float*)d_in[9];
    const float* Wl2 = (const float*)d_in[10];
    const float* bl2 = (const float*)d_in[11];
    const float* Wr2 = (const float*)d_in[12];
    const float* br2 = (const float*)d_in[13];
    const float* We2 = (const float*)d_in[14];
    const float* att2 = (const float*)d_in[15];
    const float* b2 = (const float*)d_in[16];
    const float* Rw2 = (const float*)d_in[17];
    const float* Wl3 = (const float*)d_in[18];
    const float* bl3 = (const float*)d_in[19];
    const float* Wr3 = (const float*)d_in[20];
    const float* br3 = (const float*)d_in[21];
    const float* We3 = (const float*)d_in[22];
    const float* att3 = (const float*)d_in[23];
    const float* b3 = (const float*)d_in[24];

    int Nn = in_sizes[0] / 16;   // 50000
    int Ee = in_sizes[1] / 2;    // 800000
    const int* srcp = eidx;
    const int* dstp = eidx + Ee;

    float *xl, *xr, *res, *h1, *h2, *loopw;
    int *deg, *rowptr, *wptr, *bsum;
    int2* colv;
    cudaGetSymbolAddress((void**)&xl, g_xl);
    cudaGetSymbolAddress((void**)&xr, g_xr);
    cudaGetSymbolAddress((void**)&res, g_res);
    cudaGetSymbolAddress((void**)&h1, g_h1);
    cudaGetSymbolAddress((void**)&h2, g_h2);
    cudaGetSymbolAddress((void**)&loopw, g_loop);
    cudaGetSymbolAddress((void**)&deg, g_deg);
    cudaGetSymbolAddress((void**)&rowptr, g_rowptr);
    cudaGetSymbolAddress((void**)&wptr, g_wptr);
    cudaGetSymbolAddress((void**)&bsum, g_bsum);
    cudaGetSymbolAddress((void**)&colv, g_col);

    int G = (Nn + 1023) / 1024;  // 49

    // ---- CSR + self-loop attr ----
    cudaMemsetAsync(deg, 0, Nn * sizeof(int));
    cudaMemsetAsync(loopw, 0, (size_t)Nn * 8 * sizeof(float));
    hist2_kernel<<<(Ee + 255) / 256, 256>>>(dstp, eattr, deg, loopw, Ee);
    blocksum_kernel<<<G, 1024>>>(deg, bsum, Nn);
    scanpart_kernel<<<1, 1024>>>(bsum, G);
    scanfinal_kernel<<<G, 1024>>>(deg, bsum, rowptr, wptr, Nn, Ee);
    scatter_kernel<<<(Ee + 255) / 256, 256>>>(srcp, dstp, wptr, colv, Ee);
    loopfin_kernel<<<(Nn * 8 + 255) / 256, 256>>>(deg, loopw, Nn * 8);

    int aggGrid = (Nn + 7) / 8;
    int gemmGrid = (Nn + 31) / 32;

    // ---- layer 1: in=16 -> D=32 (H=4), relu ----
    gemm_multi<16, 32, 2, 32, 16><<<gemmGrid, 128>>>(x, Wl1, bl1, xl, Wr1, br1, xr, Nn);
    agg_kernel<1, 8, true><<<aggGrid, 256>>>(xl, xr, eattr, We1, att1, b1, nullptr,
                                             rowptr, colv, loopw, h1, Nn);

    // ---- layer 2: in=32 -> D=128 (H=4), residual h1@Rw2 + b2, relu ----
    gemm_multi<32, 128, 1, 32, 32><<<gemmGrid, 256>>>(h1, Wl2, bl2, xl, nullptr, nullptr, nullptr, Nn);
    gemm_multi<32, 128, 1, 32, 32><<<gemmGrid, 256>>>(h1, Wr2, br2, xr, nullptr, nullptr, nullptr, Nn);
    gemm_multi<32, 128, 1, 32, 32><<<gemmGrid, 256>>>(h1, Rw2, b2, res, nullptr, nullptr, nullptr, Nn);
    agg_kernel<4, 8, true><<<aggGrid, 256>>>(xl, xr, eattr, We2, att2, nullptr, res,
                                             rowptr, colv, loopw, h2, Nn);

    // ---- layer 3: in=128 -> D=32 (H=1), no relu ----
    gemm_multi<128, 32, 2, 32, 32><<<gemmGrid, 128>>>(h2, Wl3, bl3, xl, Wr3, br3, xr, Nn);
    agg_kernel<1, 32, false><<<aggGrid, 256>>>(xl, xr, eattr, We3, att3, b3, nullptr,
                                               rowptr, colv, loopw, (float*)d_out, Nn);
}

// round 6
// speedup vs baseline: 1.5363x; 1.0742x over previous
#include <cuda_runtime.h>
#include <math.h>

#define NNODES 50000
#define NEDGES 800000

// ---------------- scratch (static __device__ — no allocations) ----------------
__device__ __align__(16) float g_xl[NNODES * 128];
__device__ __align__(16) float g_xr[NNODES * 128];
__device__ __align__(16) float g_res[NNODES * 128];
__device__ __align__(16) float g_h1[NNODES * 32];
__device__ __align__(16) float g_h2[NNODES * 128];
__device__ __align__(16) float g_loop[NNODES * 8];
__device__ __align__(16) float g_eaP[NEDGES * 8];    // edge_attr permuted to CSR order
__device__ int g_deg[NNODES];
__device__ int g_rowptr[NNODES + 1];
__device__ int g_wptr[NNODES];
__device__ int g_bsum[1024];
__device__ int g_colsrc[NEDGES];

// ---------------- CSR build ----------------
__global__ void hist_kernel(const int* __restrict__ dst, int* __restrict__ deg, int e) {
    int i = blockIdx.x * blockDim.x + threadIdx.x;
    if (i < e) atomicAdd(&deg[dst[i]], 1);
}

__global__ void blocksum_kernel(const int* __restrict__ deg, int* __restrict__ bsum, int n) {
    __shared__ int sh[32];
    int tid = threadIdx.x, lane = tid & 31, wid = tid >> 5;
    int i = blockIdx.x * 1024 + tid;
    int v = (i < n) ? deg[i] : 0;
    #pragma unroll
    for (int off = 16; off > 0; off >>= 1) v += __shfl_xor_sync(0xffffffffu, v, off);
    if (lane == 0) sh[wid] = v;
    __syncthreads();
    if (wid == 0) {
        int x = sh[lane];
        #pragma unroll
        for (int off = 16; off > 0; off >>= 1) x += __shfl_xor_sync(0xffffffffu, x, off);
        if (lane == 0) bsum[blockIdx.x] = x;
    }
}

__global__ void scanpart_kernel(int* __restrict__ b, int g) {
    __shared__ int ws[32];
    int tid = threadIdx.x, lane = tid & 31, wid = tid >> 5;
    int v = (tid < g) ? b[tid] : 0;
    int x = v;
    #pragma unroll
    for (int off = 1; off < 32; off <<= 1) {
        int t = __shfl_up_sync(0xffffffffu, x, off);
        if (lane >= off) x += t;
    }
    if (lane == 31) ws[wid] = x;
    __syncthreads();
    if (wid == 0) {
        int y = ws[lane];
        #pragma unroll
        for (int off = 1; off < 32; off <<= 1) {
            int t = __shfl_up_sync(0xffffffffu, y, off);
            if (lane >= off) y += t;
        }
        ws[lane] = y;
    }
    __syncthreads();
    int excl = x - v + (wid > 0 ? ws[wid - 1] : 0);
    if (tid < g) b[tid] = excl;
}

__global__ void scanfinal_kernel(const int* __restrict__ deg, const int* __restrict__ bsum,
                                 int* __restrict__ rowptr, int* __restrict__ wptr,
                                 int n, int e) {
    __shared__ int ws[32];
    int tid = threadIdx.x, lane = tid & 31, wid = tid >> 5;
    int i = blockIdx.x * 1024 + tid;
    int v = (i < n) ? deg[i] : 0;
    int x = v;
    #pragma unroll
    for (int off = 1; off < 32; off <<= 1) {
        int t = __shfl_up_sync(0xffffffffu, x, off);
        if (lane >= off) x += t;
    }
    if (lane == 31) ws[wid] = x;
    __syncthreads();
    if (wid == 0) {
        int y = ws[lane];
        #pragma unroll
        for (int off = 1; off < 32; off <<= 1) {
            int t = __shfl_up_sync(0xffffffffu, y, off);
            if (lane >= off) y += t;
        }
        ws[lane] = y;
    }
    __syncthreads();
    int excl = x - v + (wid > 0 ? ws[wid - 1] : 0) + bsum[blockIdx.x];
    if (i < n) { rowptr[i] = excl; wptr[i] = excl; }
    if (blockIdx.x == 0 && tid == 0) rowptr[n] = e;
}

// scatter src ids AND permute edge_attr into CSR order (eaP)
__global__ void scatter_kernel(const int* __restrict__ src, const int* __restrict__ dst,
                               const float* __restrict__ eattr, int* __restrict__ wptr,
                               int* __restrict__ colsrc, float* __restrict__ eaP, int e) {
    int i = blockIdx.x * blockDim.x + threadIdx.x;
    if (i >= e) return;
    int d = dst[i];
    int p = atomicAdd(&wptr[d], 1);
    colsrc[p] = src[i];
    float4 a = *(const float4*)(eattr + (size_t)i * 8);
    float4 b = *(const float4*)(eattr + (size_t)i * 8 + 4);
    *(float4*)(eaP + (size_t)p * 8) = a;
    *(float4*)(eaP + (size_t)p * 8 + 4) = b;
}

// loop-attr mean from CSR (coalesced sequential reads of eaP), divide folded in
__global__ void loopattr_kernel(const int* __restrict__ rowptr, const float* __restrict__ eaP,
                                float* __restrict__ loopv, int n) {
    int tid = blockIdx.x * blockDim.x + threadIdx.x;
    int g = tid >> 3, c = tid & 7;
    if (g >= n) return;
    int rs = rowptr[g], re = rowptr[g + 1];
    float s = 0.f;
    for (int k = rs; k < re; k++) s += eaP[(size_t)k * 8 + c];
    int d = re - rs;
    loopv[g * 8 + c] = s / (float)(d > 0 ? d : 1);
}

// ---------------- dense GEMM: up to NW weight sets sharing A ----------------
template <int K, int DOUT, int NW, int ROWS, int KC>
__global__ void gemm_multi(const float* __restrict__ A,
                           const float* __restrict__ W0, const float* __restrict__ b0, float* __restrict__ O0,
                           const float* __restrict__ W1, const float* __restrict__ b1, float* __restrict__ O1,
                           const float* __restrict__ W2, const float* __restrict__ b2, float* __restrict__ O2,
                           int n) {
    constexpr int COLS = DOUT * NW;
    constexpr int TX = COLS / 4;
    constexpr int TY = ROWS / 4;
    constexpr int NT = TX * TY;
    constexpr bool STAGE = (K * COLS * 4 <= 40960);
    constexpr int SWSZ = STAGE ? K * COLS : 1;
    __shared__ float sW[SWSZ];
    __shared__ float sA[KC][ROWS + 1];
    int tid = threadIdx.x;
    if (STAGE) {
        for (int idx = tid; idx < K * DOUT; idx += NT) {
            int k = idx / DOUT, c = idx % DOUT;
            sW[k * COLS + c] = W0[idx];
            if (NW > 1) sW[k * COLS + DOUT + c] = W1[idx];
            if (NW > 2) sW[k * COLS + 2 * DOUT + c] = W2[idx];
        }
    }
    int tx = tid % TX, ty = tid / TX;
    int cg = tx * 4;
    int which = cg / DOUT, col = cg % DOUT;
    const float* bb = (which == 0) ? b0 : (which == 1) ? b1 : b2;
    const float* Wp = (which == 0) ? W0 : (which == 1) ? W1 : W2;
    int row0 = blockIdx.x * ROWS;

    float acc[4][4];
    #pragma unroll
    for (int i = 0; i < 4; i++)
        #pragma unroll
        for (int j = 0; j < 4; j++) acc[i][j] = bb[col + j];

    for (int kc0 = 0; kc0 < K; kc0 += KC) {
        __syncthreads();
        for (int idx = tid; idx < ROWS * KC; idx += NT) {
            int r = idx / KC, k = idx % KC;
            int gr = row0 + r;
            sA[k][r] = (gr < n) ? A[(size_t)gr * K + kc0 + k] : 0.f;
        }
        __syncthreads();
        #pragma unroll
        for (int k = 0; k < KC; k++) {
            float4 rb;
            if (STAGE) rb = *(const float4*)&sW[(kc0 + k) * COLS + cg];
            else       rb = __ldg((const float4*)&Wp[(size_t)(kc0 + k) * DOUT + col]);
            float ra0 = sA[k][ty * 4 + 0];
            float ra1 = sA[k][ty * 4 + 1];
            float ra2 = sA[k][ty * 4 + 2];
            float ra3 = sA[k][ty * 4 + 3];
            acc[0][0] = fmaf(ra0, rb.x, acc[0][0]); acc[0][1] = fmaf(ra0, rb.y, acc[0][1]);
            acc[0][2] = fmaf(ra0, rb.z, acc[0][2]); acc[0][3] = fmaf(ra0, rb.w, acc[0][3]);
            acc[1][0] = fmaf(ra1, rb.x, acc[1][0]); acc[1][1] = fmaf(ra1, rb.y, acc[1][1]);
            acc[1][2] = fmaf(ra1, rb.z, acc[1][2]); acc[1][3] = fmaf(ra1, rb.w, acc[1][3]);
            acc[2][0] = fmaf(ra2, rb.x, acc[2][0]); acc[2][1] = fmaf(ra2, rb.y, acc[2][1]);
            acc[2][2] = fmaf(ra2, rb.z, acc[2][2]); acc[2][3] = fmaf(ra2, rb.w, acc[2][3]);
            acc[3][0] = fmaf(ra3, rb.x, acc[3][0]); acc[3][1] = fmaf(ra3, rb.y, acc[3][1]);
            acc[3][2] = fmaf(ra3, rb.z, acc[3][2]); acc[3][3] = fmaf(ra3, rb.w, acc[3][3]);
        }
    }
    float* O = (which == 0) ? O0 : (which == 1) ? O1 : O2;
    #pragma unroll
    for (int i = 0; i < 4; i++) {
        int gr = row0 + ty * 4 + i;
        if (gr < n)
            *(float4*)&O[(size_t)gr * DOUT + col] =
                make_float4(acc[i][0], acc[i][1], acc[i][2], acc[i][3]);
    }
}

// ---------------- fused GATv2 edge pass: warp per destination, We in registers ----------------
template <int VEC, int GROUP, bool RELU>
__global__ __launch_bounds__(256) void agg_kernel(
    const float* __restrict__ xl, const float* __restrict__ xr,
    const float* __restrict__ eaP, const float* __restrict__ We,
    const float* __restrict__ att, const float* __restrict__ bias,
    const float* __restrict__ pre, const int* __restrict__ rowptr,
    const int* __restrict__ colsrc, const float* __restrict__ loopattr,
    float* __restrict__ out, int n) {
    constexpr int D = 32 * VEC;
    int tid = threadIdx.x, lane = tid & 31, wid = tid >> 5;
    int dst = blockIdx.x * 8 + wid;
    if (dst >= n) return;

    const int c0 = lane * VEC;

    // We in registers: loaded once per warp lifetime (no smem, no per-edge LDS)
    float rWe[8][VEC];
    #pragma unroll
    for (int q = 0; q < 8; q++) {
        if (VEC == 4) {
            float4 w = __ldg((const float4*)(We + q * D + c0));
            rWe[q][0] = w.x; rWe[q][1] = w.y; rWe[q][2] = w.z; rWe[q][3] = w.w;
        } else {
            rWe[q][0] = __ldg(We + q * 32 + lane);
        }
    }

    float attv[VEC], xrv[VEC], num[VEC];
    float den = 0.f;
    if (VEC == 4) {
        float4 a = *(const float4*)(att + c0);
        attv[0] = a.x; attv[1] = a.y; attv[2] = a.z; attv[3] = a.w;
        float4 r = *(const float4*)(xr + (size_t)dst * D + c0);
        xrv[0] = r.x; xrv[1] = r.y; xrv[2] = r.z; xrv[3] = r.w;
    } else {
        attv[0] = att[c0];
        xrv[0] = xr[(size_t)dst * D + c0];
    }
    #pragma unroll
    for (int v = 0; v < VEC; v++) num[v] = 0.f;

    auto ldX = [&](float* d, const float* p) {
        if (VEC == 4) {
            float4 t = *(const float4*)p;
            d[0] = t.x; d[1] = t.y; d[2] = t.z; d[3] = t.w;
        } else d[0] = p[0];
    };
    auto ldE = [&](float* d, const float* p) {
        float4 a = *(const float4*)p;
        float4 b = *(const float4*)(p + 4);
        d[0] = a.x; d[1] = a.y; d[2] = a.z; d[3] = a.w;
        d[4] = b.x; d[5] = b.y; d[6] = b.z; d[7] = b.w;
    };
    auto body = [&](const float* xv, const float* ev) {
        float m[VEC];
        #pragma unroll
        for (int v = 0; v < VEC; v++) m[v] = 0.f;
        #pragma unroll
        for (int q = 0; q < 8; q++)
            #pragma unroll
            for (int v = 0; v < VEC; v++)
                m[v] = fmaf(ev[q], rWe[q][v], m[v]);
        float p = 0.f;
        #pragma unroll
        for (int v = 0; v < VEC; v++) {
            float t = m[v] + xv[v] + xrv[v];
            float s = fmaxf(t, 0.f) + 0.2f * fminf(t, 0.f);
            p = fmaf(s, attv[v], p);
        }
        #pragma unroll
        for (int off = GROUP / 2; off > 0; off >>= 1)
            p += __shfl_xor_sync(0xffffffffu, p, off);
        float w = __expf(p);
        #pragma unroll
        for (int v = 0; v < VEC; v++) num[v] = fmaf(w, xv[v], num[v]);
        den += w;
    };

    int rs = rowptr[dst], re = rowptr[dst + 1];

    // depth-2 pipeline, compile-time slot indices (manual 2x unroll)
    float px0[VEC], pe0[8], px1[VEC], pe1[8];
    if (rs < re) {
        int s = colsrc[rs];
        ldE(pe0, eaP + (size_t)rs * 8);
        ldX(px0, xl + (size_t)s * D + c0);
    }
    if (rs + 1 < re) {
        int s = colsrc[rs + 1];
        ldE(pe1, eaP + (size_t)(rs + 1) * 8);
        ldX(px1, xl + (size_t)s * D + c0);
    }
    {   // self loop (its loads overlap the prefetches above)
        float sx[VEC], se[8];
        ldX(sx, xl + (size_t)dst * D + c0);
        ldE(se, loopattr + (size_t)dst * 8);
        body(sx, se);
    }
    int k = rs;
    while (k < re) {
        {   // consume slot 0
            float cx[VEC], ce[8];
            #pragma unroll
            for (int v = 0; v < VEC; v++) cx[v] = px0[v];
            #pragma unroll
            for (int q = 0; q < 8; q++) ce[q] = pe0[q];
            if (k + 2 < re) {
                int s = colsrc[k + 2];
                ldE(pe0, eaP + (size_t)(k + 2) * 8);
                ldX(px0, xl + (size_t)s * D + c0);
            }
            body(cx, ce);
        }
        k++;
        if (k >= re) break;
        {   // consume slot 1
            float cx[VEC], ce[8];
            #pragma unroll
            for (int v = 0; v < VEC; v++) cx[v] = px1[v];
            #pragma unroll
            for (int q = 0; q < 8; q++) ce[q] = pe1[q];
            if (k + 2 < re) {
                int s = colsrc[k + 2];
                ldE(pe1, eaP + (size_t)(k + 2) * 8);
                ldX(px1, xl + (size_t)s * D + c0);
            }
            body(cx, ce);
        }
        k++;
    }

    float res[VEC];
    #pragma unroll
    for (int v = 0; v < VEC; v++) {
        float val = num[v] / den;
        if (bias) val += bias[c0 + v];
        if (pre) val += pre[(size_t)dst * D + c0 + v];
        if (RELU) val = fmaxf(val, 0.f);
        res[v] = val;
    }
    if (VEC == 4)
        *(float4*)&out[(size_t)dst * D + c0] = make_float4(res[0], res[1], res[2], res[3]);
    else
        out[(size_t)dst * D + c0] = res[0];
}

// ---------------- host launcher ----------------
extern "C" void kernel_launch(void* const* d_in, const int* in_sizes, int n_in,
                              void* d_out, int out_size) {
    const float* x     = (const float*)d_in[0];
    const int*   eidx  = (const int*)d_in[1];
    const float* eattr = (const float*)d_in[2];
    const float* Wl1 = (const float*)d_in[3];
    const float* bl1 = (const float*)d_in[4];
    const float* Wr1 = (const float*)d_in[5];
    const float* br1 = (const float*)d_in[6];
    const float* We1 = (const float*)d_in[7];
    const float* att1 = (const float*)d_in[8];
    const float* b1 = (const float*)d_in[9];
    const float* Wl2 = (const float*)d_in[10];
    const float* bl2 = (const float*)d_in[11];
    const float* Wr2 = (const float*)d_in[12];
    const float* br2 = (const float*)d_in[13];
    const float* We2 = (const float*)d_in[14];
    const float* att2 = (const float*)d_in[15];
    const float* b2 = (const float*)d_in[16];
    const float* Rw2 = (const float*)d_in[17];
    const float* Wl3 = (const float*)d_in[18];
    const float* bl3 = (const float*)d_in[19];
    const float* Wr3 = (const float*)d_in[20];
    const float* br3 = (const float*)d_in[21];
    const float* We3 = (const float*)d_in[22];
    const float* att3 = (const float*)d_in[23];
    const float* b3 = (const float*)d_in[24];

    int Nn = in_sizes[0] / 16;   // 50000
    int Ee = in_sizes[1] / 2;    // 800000
    const int* srcp = eidx;
    const int* dstp = eidx + Ee;

    float *xl, *xr, *res, *h1, *h2, *loopw, *eaP;
    int *deg, *rowptr, *wptr, *bsum, *colsrc;
    cudaGetSymbolAddress((void**)&xl, g_xl);
    cudaGetSymbolAddress((void**)&xr, g_xr);
    cudaGetSymbolAddress((void**)&res, g_res);
    cudaGetSymbolAddress((void**)&h1, g_h1);
    cudaGetSymbolAddress((void**)&h2, g_h2);
    cudaGetSymbolAddress((void**)&loopw, g_loop);
    cudaGetSymbolAddress((void**)&eaP, g_eaP);
    cudaGetSymbolAddress((void**)&deg, g_deg);
    cudaGetSymbolAddress((void**)&rowptr, g_rowptr);
    cudaGetSymbolAddress((void**)&wptr, g_wptr);
    cudaGetSymbolAddress((void**)&bsum, g_bsum);
    cudaGetSymbolAddress((void**)&colsrc, g_colsrc);

    int G = (Nn + 1023) / 1024;  // 49

    // ---- CSR + permuted eattr + self-loop attr ----
    cudaMemsetAsync(deg, 0, Nn * sizeof(int));
    hist_kernel<<<(Ee + 255) / 256, 256>>>(dstp, deg, Ee);
    blocksum_kernel<<<G, 1024>>>(deg, bsum, Nn);
    scanpart_kernel<<<1, 1024>>>(bsum, G);
    scanfinal_kernel<<<G, 1024>>>(deg, bsum, rowptr, wptr, Nn, Ee);
    scatter_kernel<<<(Ee + 255) / 256, 256>>>(srcp, dstp, eattr, wptr, colsrc, eaP, Ee);
    loopattr_kernel<<<(Nn * 8 + 255) / 256, 256>>>(rowptr, eaP, loopw, Nn);

    int aggGrid = (Nn + 7) / 8;

    // ---- layer 1: in=16 -> D=32 (H=4), relu ----
    gemm_multi<16, 32, 2, 32, 16><<<(Nn + 31) / 32, 128>>>(
        x, Wl1, bl1, xl, Wr1, br1, xr, nullptr, nullptr, nullptr, Nn);
    agg_kernel<1, 8, true><<<aggGrid, 256>>>(xl, xr, eaP, We1, att1, b1, nullptr,
                                             rowptr, colsrc, loopw, h1, Nn);

    // ---- layer 2: in=32 -> D=128 (H=4), residual h1@Rw2 + b2, relu (3 GEMMs fused) ----
    gemm_multi<32, 128, 3, 16, 32><<<(Nn + 15) / 16, 384>>>(
        h1, Wl2, bl2, xl, Wr2, br2, xr, Rw2, b2, res, Nn);
    agg_kernel<4, 8, true><<<aggGrid, 256>>>(xl, xr, eaP, We2, att2, nullptr, res,
                                             rowptr, colsrc, loopw, h2, Nn);

    // ---- layer 3: in=128 -> D=32 (H=1), no relu ----
    gemm_multi<128, 32, 2, 32, 32><<<(Nn + 31) / 32, 128>>>(
        h2, Wl3, bl3, xl, Wr3, br3, xr, nullptr, nullptr, nullptr, Nn);
    agg_kernel<1, 32, false><<<aggGrid, 256>>>(xl, xr, eaP, We3, att3, b3, nullptr,
                                               rowptr, colsrc, loopw, (float*)d_out, Nn);
}